// round 13
// baseline (speedup 1.0000x reference)
#include <cuda_runtime.h>
#include <cuda_bf16.h>
#include <mma.h>
#include <cstdint>
#include <math.h>

using namespace nvcuda;

#define NB 2
#define SLEN 2048
#define NHEADS 16
#define HDIM 64
#define EMB 1024
#define NH (NB * NHEADS)
#define NROWS (NB * SLEN * NHEADS)

// ---------------------------------------------------------------------------
// Global scratch (allocation-free rule: __device__ globals)
// ---------------------------------------------------------------------------
__device__ __align__(16) __nv_bfloat16 g_qh[(size_t)NH * SLEN * HDIM];
__device__ __align__(16) __nv_bfloat16 g_ql[(size_t)NH * SLEN * HDIM];
__device__ __align__(16) __nv_bfloat16 g_kh[(size_t)NH * SLEN * HDIM];
__device__ __align__(16) __nv_bfloat16 g_kl[(size_t)NH * SLEN * HDIM];
__device__ __align__(16) __nv_bfloat16 g_vh[(size_t)NH * SLEN * HDIM];
__device__ __align__(16) __nv_bfloat16 g_vl[(size_t)NH * SLEN * HDIM];
__device__ __align__(16) __nv_bfloat16 g_oh[(size_t)NB * SLEN * EMB];   // attn out hi
__device__ __align__(16) __nv_bfloat16 g_ol[(size_t)NB * SLEN * EMB];   // attn out lo
__device__ __align__(16) __nv_bfloat16 g_woth[(size_t)EMB * EMB];       // Wo^T hi (e,k)
__device__ __align__(16) __nv_bfloat16 g_wotl[(size_t)EMB * EMB];       // Wo^T lo (e,k)

__device__ __forceinline__ uint32_t pack_bf2(float a, float b) {
    __nv_bfloat16 x = __float2bfloat16(a), y = __float2bfloat16(b);
    return ((uint32_t)__bfloat16_as_ushort(y) << 16) | (uint32_t)__bfloat16_as_ushort(x);
}
__device__ __forceinline__ float bf_round(float a) {
    return __bfloat162float(__float2bfloat16(a));
}

// ---------------------------------------------------------------------------
// Kernel 1: per-head projection -> bf16 hi/lo splits in (N,H,S,D)
// ---------------------------------------------------------------------------
__global__ __launch_bounds__(256) void proj_kernel(
    const float* __restrict__ in, const float* __restrict__ W,
    const float* __restrict__ bias, int which, float scale)
{
    __shared__ float in_s[64 * 65];
    __shared__ float w_s[64 * 64];

    __nv_bfloat16* outh = (which == 0) ? g_vh : (which == 1) ? g_kh : g_qh;
    __nv_bfloat16* outl = (which == 0) ? g_vl : (which == 1) ? g_kl : g_ql;

    int t = threadIdx.x;
    int rowBase = blockIdx.x * 64;

    for (int i = t; i < 4096; i += 256) w_s[i] = W[i];
    for (int i = t; i < 4096; i += 256) {
        int r = i >> 6, k = i & 63;
        in_s[r * 65 + k] = in[(size_t)rowBase * 64 + i];
    }
    __syncthreads();

    int tr = t >> 4, tc = t & 15;
    int r0 = tr * 4, c0 = tc * 4;

    float acc[4][4];
    #pragma unroll
    for (int u = 0; u < 4; u++)
        #pragma unroll
        for (int v = 0; v < 4; v++) acc[u][v] = bias[c0 + v];

    #pragma unroll 8
    for (int k = 0; k < 64; k++) {
        float4 b = *(const float4*)&w_s[k * 64 + c0];
        float a[4];
        #pragma unroll
        for (int u = 0; u < 4; u++) a[u] = in_s[(r0 + u) * 65 + k];
        #pragma unroll
        for (int u = 0; u < 4; u++) {
            acc[u][0] += a[u] * b.x; acc[u][1] += a[u] * b.y;
            acc[u][2] += a[u] * b.z; acc[u][3] += a[u] * b.w;
        }
    }

    #pragma unroll
    for (int u = 0; u < 4; u++) {
        int row = rowBase + r0 + u;
        int n = row >> 15;
        int rem = row & 32767;
        int s = rem >> 4;
        int h = rem & 15;
        size_t base = (((size_t)(n * NHEADS + h)) * SLEN + s) * HDIM + c0;
        float v0 = acc[u][0] * scale, v1 = acc[u][1] * scale;
        float v2 = acc[u][2] * scale, v3 = acc[u][3] * scale;
        *(uint32_t*)&outh[base + 0] = pack_bf2(v0, v1);
        *(uint32_t*)&outh[base + 2] = pack_bf2(v2, v3);
        *(uint32_t*)&outl[base + 0] = pack_bf2(v0 - bf_round(v0), v1 - bf_round(v1));
        *(uint32_t*)&outl[base + 2] = pack_bf2(v2 - bf_round(v2), v3 - bf_round(v3));
    }
}

// ---------------------------------------------------------------------------
// Kernel 2: transpose + split Wo -> WoT hi/lo (e,k)
// ---------------------------------------------------------------------------
__global__ __launch_bounds__(256) void wo_convert(const float* __restrict__ Wo)
{
    __shared__ float ts[64 * 65];
    int t = threadIdx.x;
    int kb = blockIdx.x * 64, eb = blockIdx.y * 64;
    for (int i = t; i < 4096; i += 256) {
        int r = i >> 6, c = i & 63;
        ts[c * 65 + r] = Wo[(size_t)(kb + r) * EMB + eb + c];
    }
    __syncthreads();
    for (int i = t; i < 4096; i += 256) {
        int e = i >> 6, k = i & 63;
        float v = ts[e * 65 + k];
        size_t o = (size_t)(eb + e) * EMB + kb + k;
        g_woth[o] = __float2bfloat16(v);
        g_wotl[o] = __float2bfloat16(v - bf_round(v));
    }
}

// ---------------------------------------------------------------------------
// Kernel 3: WMMA flash attention. CTA = (qt, nh): 128 q-rows x full S.
// KV tile = 128, Q fragments hoisted. sf aliased over DEAD Q staging area,
// ph/pl have their OWN storage -> softmax is one phase, no f[] across barrier.
// 207KB smem, 1 CTA/SM, 4 syncs/tile.
// ---------------------------------------------------------------------------
#define LDH 72                 // bf16 ldm for 64-col arrays (Q,K,V)
#define LDP 136                // bf16 ldm for 128-col P
#define LDSF 132               // f32 ldm for 128-col scores

#define TS 128                 // KV tile size

#define A_SF 0                                    // f32 128 x 132 = 67584 B
#define A_QH 0                                    // Q staging (dead after frag hoist)
#define A_QL (A_QH + 128 * LDH * 2)               // 18432 (inside sf region)
#define A_KH 67584
#define A_KL (A_KH + TS * LDH * 2)                // 86016
#define A_VH (A_KL + TS * LDH * 2)                // 104448
#define A_VL (A_VH + TS * LDH * 2)                // 122880
#define A_PH (A_VL + TS * LDH * 2)                // 141312
#define A_PL (A_PH + 128 * LDP * 2)               // 176128
#define A_LS (A_PL + 128 * LDP * 2)               // 210944
#define ATTN_SMEM (A_LS + 256 * 4)                // 211968 (207KB) -> 1 CTA/SM

typedef wmma::fragment<wmma::matrix_a, 16, 16, 16, __nv_bfloat16, wmma::row_major> FragA;
typedef wmma::fragment<wmma::matrix_b, 16, 16, 16, __nv_bfloat16, wmma::col_major> FragBC;
typedef wmma::fragment<wmma::matrix_b, 16, 16, 16, __nv_bfloat16, wmma::row_major> FragBR;
typedef wmma::fragment<wmma::accumulator, 16, 16, 16, float> FragC;

__global__ __launch_bounds__(256) void attn_wmma(const float* __restrict__ mask)
{
    extern __shared__ char smem[];
    __nv_bfloat16* qh = (__nv_bfloat16*)(smem + A_QH);
    __nv_bfloat16* ql = (__nv_bfloat16*)(smem + A_QL);
    __nv_bfloat16* kh = (__nv_bfloat16*)(smem + A_KH);
    __nv_bfloat16* kl = (__nv_bfloat16*)(smem + A_KL);
    __nv_bfloat16* vh = (__nv_bfloat16*)(smem + A_VH);
    __nv_bfloat16* vl = (__nv_bfloat16*)(smem + A_VL);
    __nv_bfloat16* ph = (__nv_bfloat16*)(smem + A_PH);
    __nv_bfloat16* pl = (__nv_bfloat16*)(smem + A_PL);
    float*         sf = (float*)(smem + A_SF);
    float*         ls = (float*)(smem + A_LS);

    int t = threadIdx.x;
    int w = t >> 5;
    int row = t & 127;       // softmax row
    int half = t >> 7;       // 0: cols 0..63, 1: cols 64..127 (of the 128-tile)
    int qt = blockIdx.x;     // 0..15
    int nh = blockIdx.y;     // 0..31

    // stage Q hi/lo (128 x 64 bf16 each) into the sf region (Q dies after hoist)
    {
        const __nv_bfloat16* gqh = g_qh + ((size_t)nh * SLEN + (size_t)qt * 128) * HDIM;
        const __nv_bfloat16* gql = g_ql + ((size_t)nh * SLEN + (size_t)qt * 128) * HDIM;
        for (int i = t; i < 1024; i += 256) {
            int r = i >> 3, c = i & 7;
            *(uint4*)(qh + r * LDH + c * 8) = *(const uint4*)(gqh + (size_t)r * 64 + c * 8);
            *(uint4*)(ql + r * LDH + c * 8) = *(const uint4*)(gql + (size_t)r * 64 + c * 8);
        }
    }
    __syncthreads();

    // hoist Q fragments: loop-invariant across all KV tiles
    FragA aH[4], aL[4];
    #pragma unroll
    for (int kf = 0; kf < 4; kf++) {
        wmma::load_matrix_sync(aH[kf], qh + (w * 16) * LDH + kf * 16, LDH);
        wmma::load_matrix_sync(aL[kf], ql + (w * 16) * LDH + kf * 16, LDH);
    }
    // NOTE: no extra sync needed here: the sync after the first K/V load below
    // orders every thread's fragment loads before any sf store.

    float lsum = 0.f;
    FragC oacc[4];
    #pragma unroll
    for (int n = 0; n < 4; n++) wmma::fill_fragment(oacc[n], 0.f);

    const float* mrow = mask + (size_t)(qt * 128 + row) * SLEN + half * 64;

    for (int kt = 0; kt < SLEN / TS; kt++) {
        // --- load K/V hi/lo tiles (128 x 64 bf16 each) ---
        {
            size_t gb = ((size_t)nh * SLEN + (size_t)kt * TS) * HDIM;
            for (int i = t; i < 1024; i += 256) {
                int r = i >> 3, c = i & 7;
                size_t g = gb + (size_t)r * 64 + c * 8;
                int s = r * LDH + c * 8;
                *(uint4*)(kh + s) = *(const uint4*)(g_kh + g);
                *(uint4*)(kl + s) = *(const uint4*)(g_kl + g);
                *(uint4*)(vh + s) = *(const uint4*)(g_vh + g);
                *(uint4*)(vl + s) = *(const uint4*)(g_vl + g);
            }
        }
        __syncthreads();

        // --- S = Qh.Kh^T + Qh.Kl^T + Ql.Kh^T  (128x128) -> sf ---
        {
            FragC sacc[8];
            #pragma unroll
            for (int n = 0; n < 8; n++) wmma::fill_fragment(sacc[n], 0.f);

            #pragma unroll
            for (int n = 0; n < 8; n++) {
                #pragma unroll
                for (int kf = 0; kf < 4; kf++) {
                    FragBC bH, bL;
                    wmma::load_matrix_sync(bH, kh + (n * 16) * LDH + kf * 16, LDH);
                    wmma::mma_sync(sacc[n], aH[kf], bH, sacc[n]);
                    wmma::mma_sync(sacc[n], aL[kf], bH, sacc[n]);
                    wmma::load_matrix_sync(bL, kl + (n * 16) * LDH + kf * 16, LDH);
                    wmma::mma_sync(sacc[n], aH[kf], bL, sacc[n]);
                }
            }
            #pragma unroll
            for (int n = 0; n < 8; n++)
                wmma::store_matrix_sync(sf + (w * 16) * LDSF + n * 16, sacc[n], LDSF, wmma::mem_row_major);
        }
        __syncthreads();

        // --- softmax: single phase (sf and P no longer alias) ---
        {
            const float4* srow = (const float4*)(sf + row * LDSF + half * 64);
            const float4* mk4 = (const float4*)(mrow + kt * TS);
            uint4* phv = (uint4*)(ph + row * LDP + half * 64);
            uint4* plv = (uint4*)(pl + row * LDP + half * 64);
            #pragma unroll
            for (int j = 0; j < 8; j++) {
                float4 s0 = srow[2 * j],     m0 = mk4[2 * j];
                float4 s1 = srow[2 * j + 1], m1 = mk4[2 * j + 1];
                float e0 = __expf(s0.x * m0.x);
                float e1 = __expf(s0.y * m0.y);
                float e2 = __expf(s0.z * m0.z);
                float e3 = __expf(s0.w * m0.w);
                float e4 = __expf(s1.x * m1.x);
                float e5 = __expf(s1.y * m1.y);
                float e6 = __expf(s1.z * m1.z);
                float e7 = __expf(s1.w * m1.w);
                lsum += (e0 + e1 + e2 + e3) + (e4 + e5 + e6 + e7);
                phv[j] = make_uint4(pack_bf2(e0, e1), pack_bf2(e2, e3),
                                    pack_bf2(e4, e5), pack_bf2(e6, e7));
                plv[j] = make_uint4(
                    pack_bf2(e0 - bf_round(e0), e1 - bf_round(e1)),
                    pack_bf2(e2 - bf_round(e2), e3 - bf_round(e3)),
                    pack_bf2(e4 - bf_round(e4), e5 - bf_round(e5)),
                    pack_bf2(e6 - bf_round(e6), e7 - bf_round(e7)));
            }
        }
        __syncthreads();

        // --- O += Ph.Vh + Ph.Vl + Pl.Vh  (128x64, K-dim = 128) ---
        {
            #pragma unroll
            for (int kf = 0; kf < 8; kf++) {
                FragA pH, pL;
                wmma::load_matrix_sync(pH, ph + (w * 16) * LDP + kf * 16, LDP);
                wmma::load_matrix_sync(pL, pl + (w * 16) * LDP + kf * 16, LDP);
                #pragma unroll
                for (int n = 0; n < 4; n++) {
                    FragBR bH, bL;
                    wmma::load_matrix_sync(bH, vh + (kf * 16) * LDH + n * 16, LDH);
                    wmma::mma_sync(oacc[n], pH, bH, oacc[n]);
                    wmma::mma_sync(oacc[n], pL, bH, oacc[n]);
                    wmma::load_matrix_sync(bL, vl + (kf * 16) * LDH + n * 16, LDH);
                    wmma::mma_sync(oacc[n], pH, bL, oacc[n]);
                }
            }
        }
        __syncthreads();   // before next tile overwrites K/V (and sf by QK store)
    }

    // --- epilogue: combine lsum halves, normalize, split, store ---
    ls[t] = lsum;          // index = half*128 + row
    #pragma unroll
    for (int n = 0; n < 4; n++)
        wmma::store_matrix_sync(sf + (w * 16) * LDSF + n * 16, oacc[n], LDSF, wmma::mem_row_major);
    __syncthreads();

    {
        float inv = 1.f / (ls[row] + ls[128 + row]);
        int n = nh >> 4, h = nh & 15;
        size_t gbase = ((size_t)n * SLEN + (size_t)qt * 128 + row) * EMB + h * 64 + half * 32;
        const float* srow = sf + row * LDSF + half * 32;
        #pragma unroll
        for (int j = 0; j < 4; j++) {
            float4 s0 = ((const float4*)srow)[2 * j];
            float4 s1 = ((const float4*)srow)[2 * j + 1];
            float o0 = s0.x * inv, o1 = s0.y * inv, o2 = s0.z * inv, o3 = s0.w * inv;
            float o4 = s1.x * inv, o5 = s1.y * inv, o6 = s1.z * inv, o7 = s1.w * inv;
            *(uint4*)(g_oh + gbase + j * 8) = make_uint4(
                pack_bf2(o0, o1), pack_bf2(o2, o3), pack_bf2(o4, o5), pack_bf2(o6, o7));
            *(uint4*)(g_ol + gbase + j * 8) = make_uint4(
                pack_bf2(o0 - bf_round(o0), o1 - bf_round(o1)),
                pack_bf2(o2 - bf_round(o2), o3 - bf_round(o3)),
                pack_bf2(o4 - bf_round(o4), o5 - bf_round(o5)),
                pack_bf2(o6 - bf_round(o6), o7 - bf_round(o7)));
        }
    }
}

// ---------------------------------------------------------------------------
// Kernel 4: output projection out[m][e] = att[m][:] . WoT[e][:] + bo[e]
// CTA = (et, mt): 128 m-rows x 64 e-cols, K=1024 in 16 chunks of 64.
// ---------------------------------------------------------------------------
#define LDS 68
#define P_AH 0
#define P_AL (P_AH + 128 * LDH * 2)
#define P_BH (P_AL + 128 * LDH * 2)
#define P_BL (P_BH + 64 * LDH * 2)
#define P_SF (P_BL + 64 * LDH * 2)
#define PROJ_SMEM (P_SF + 128 * LDS * 4)     // 90112

__global__ __launch_bounds__(256) void outproj_wmma(
    const float* __restrict__ bo, float* __restrict__ out)
{
    extern __shared__ char smem[];
    __nv_bfloat16* ah = (__nv_bfloat16*)(smem + P_AH);
    __nv_bfloat16* al = (__nv_bfloat16*)(smem + P_AL);
    __nv_bfloat16* bh = (__nv_bfloat16*)(smem + P_BH);
    __nv_bfloat16* bl = (__nv_bfloat16*)(smem + P_BL);
    float*         sf = (float*)(smem + P_SF);

    int t = threadIdx.x;
    int w = t >> 5;
    int et = blockIdx.x;    // 0..15
    int mt = blockIdx.y;    // 0..31

    FragC oacc[4];
    #pragma unroll
    for (int n = 0; n < 4; n++) wmma::fill_fragment(oacc[n], 0.f);

    for (int kt = 0; kt < EMB / 64; kt++) {
        {
            const __nv_bfloat16* gah = g_oh + (size_t)(mt * 128) * EMB + kt * 64;
            const __nv_bfloat16* gal = g_ol + (size_t)(mt * 128) * EMB + kt * 64;
            for (int i = t; i < 1024; i += 256) {
                int r = i >> 3, c = i & 7;
                *(uint4*)(ah + r * LDH + c * 8) = *(const uint4*)(gah + (size_t)r * EMB + c * 8);
                *(uint4*)(al + r * LDH + c * 8) = *(const uint4*)(gal + (size_t)r * EMB + c * 8);
            }
            const __nv_bfloat16* gbh = g_woth + (size_t)(et * 64) * EMB + kt * 64;
            const __nv_bfloat16* gbl = g_wotl + (size_t)(et * 64) * EMB + kt * 64;
            for (int i = t; i < 512; i += 256) {
                int r = i >> 3, c = i & 7;
                *(uint4*)(bh + r * LDH + c * 8) = *(const uint4*)(gbh + (size_t)r * EMB + c * 8);
                *(uint4*)(bl + r * LDH + c * 8) = *(const uint4*)(gbl + (size_t)r * EMB + c * 8);
            }
        }
        __syncthreads();

        FragA aH[4], aL[4];
        #pragma unroll
        for (int kf = 0; kf < 4; kf++) {
            wmma::load_matrix_sync(aH[kf], ah + (w * 16) * LDH + kf * 16, LDH);
            wmma::load_matrix_sync(aL[kf], al + (w * 16) * LDH + kf * 16, LDH);
        }
        #pragma unroll
        for (int n = 0; n < 4; n++) {
            #pragma unroll
            for (int kf = 0; kf < 4; kf++) {
                FragBC bH, bL;
                wmma::load_matrix_sync(bH, bh + (n * 16) * LDH + kf * 16, LDH);
                wmma::mma_sync(oacc[n], aH[kf], bH, oacc[n]);
                wmma::mma_sync(oacc[n], aL[kf], bH, oacc[n]);
                wmma::load_matrix_sync(bL, bl + (n * 16) * LDH + kf * 16, LDH);
                wmma::mma_sync(oacc[n], aH[kf], bL, oacc[n]);
            }
        }
        __syncthreads();
    }

    #pragma unroll
    for (int n = 0; n < 4; n++)
        wmma::store_matrix_sync(sf + (w * 16) * LDS + n * 16, oacc[n], LDS, wmma::mem_row_major);
    __syncthreads();

    if (t < 128) {
        size_t m = (size_t)mt * 128 + t;
        float* dst = out + m * EMB + et * 64;
        const float* srow = sf + t * LDS;
        #pragma unroll
        for (int c4 = 0; c4 < 16; c4++) {
            float4 s = ((const float4*)srow)[c4];
            float4 bb = *(const float4*)&bo[et * 64 + c4 * 4];
            *(float4*)(dst + c4 * 4) = make_float4(s.x + bb.x, s.y + bb.y, s.z + bb.z, s.w + bb.w);
        }
    }
}

// ---------------------------------------------------------------------------
extern "C" void kernel_launch(void* const* d_in, const int* in_sizes, int n_in,
                              void* d_out, int out_size)
{
    const float* values  = (const float*)d_in[0];
    const float* keys    = (const float*)d_in[1];
    const float* queries = (const float*)d_in[2];
    const float* mask    = (const float*)d_in[3];
    const float* Wv = (const float*)d_in[4];
    const float* bv = (const float*)d_in[5];
    const float* Wk = (const float*)d_in[6];
    const float* bk = (const float*)d_in[7];
    const float* Wq = (const float*)d_in[8];
    const float* bq = (const float*)d_in[9];
    const float* Wo = (const float*)d_in[10];
    const float* bo = (const float*)d_in[11];
    float* out = (float*)d_out;

    cudaFuncSetAttribute(attn_wmma, cudaFuncAttributeMaxDynamicSharedMemorySize, ATTN_SMEM);
    cudaFuncSetAttribute(outproj_wmma, cudaFuncAttributeMaxDynamicSharedMemorySize, PROJ_SMEM);

    proj_kernel<<<NROWS / 64, 256>>>(values,  Wv, bv, 0, 1.0f);
    proj_kernel<<<NROWS / 64, 256>>>(keys,    Wk, bk, 1, 1.0f);
    proj_kernel<<<NROWS / 64, 256>>>(queries, Wq, bq, 2, 0.03125f);   // fold 1/sqrt(EMB)
    wo_convert<<<dim3(16, 16), 256>>>(Wo);

    attn_wmma<<<dim3(SLEN / 128, NH), 256, ATTN_SMEM>>>(mask);

    outproj_wmma<<<dim3(EMB / 64, NB * SLEN / 128), 256, PROJ_SMEM>>>(bo, out);
}

// round 14
// speedup vs baseline: 1.9042x; 1.9042x over previous
#include <cuda_runtime.h>
#include <cuda_bf16.h>
#include <mma.h>
#include <cstdint>
#include <math.h>

using namespace nvcuda;

#define NB 2
#define SLEN 2048
#define NHEADS 16
#define HDIM 64
#define EMB 1024
#define NH (NB * NHEADS)
#define NROWS (NB * SLEN * NHEADS)

// ---------------------------------------------------------------------------
// Global scratch (allocation-free rule: __device__ globals)
// ---------------------------------------------------------------------------
__device__ __align__(16) __nv_bfloat16 g_qh[(size_t)NH * SLEN * HDIM];
__device__ __align__(16) __nv_bfloat16 g_ql[(size_t)NH * SLEN * HDIM];
__device__ __align__(16) __nv_bfloat16 g_kh[(size_t)NH * SLEN * HDIM];
__device__ __align__(16) __nv_bfloat16 g_kl[(size_t)NH * SLEN * HDIM];
__device__ __align__(16) __nv_bfloat16 g_vh[(size_t)NH * SLEN * HDIM];
__device__ __align__(16) __nv_bfloat16 g_vl[(size_t)NH * SLEN * HDIM];
__device__ __align__(16) __nv_bfloat16 g_oh[(size_t)NB * SLEN * EMB];   // attn out hi
__device__ __align__(16) __nv_bfloat16 g_ol[(size_t)NB * SLEN * EMB];   // attn out lo
__device__ __align__(16) __nv_bfloat16 g_woth[(size_t)EMB * EMB];       // Wo^T hi (e,k)
__device__ __align__(16) __nv_bfloat16 g_wotl[(size_t)EMB * EMB];       // Wo^T lo (e,k)

__device__ __forceinline__ uint32_t pack_bf2(float a, float b) {
    __nv_bfloat16 x = __float2bfloat16(a), y = __float2bfloat16(b);
    return ((uint32_t)__bfloat16_as_ushort(y) << 16) | (uint32_t)__bfloat16_as_ushort(x);
}
__device__ __forceinline__ float bf_round(float a) {
    return __bfloat162float(__float2bfloat16(a));
}

// ---- raw tensor-core primitives (sm_80+, no arch-suffix gating) ----
__device__ __forceinline__ void mma16816(float* d, const uint32_t* a, const uint32_t* b) {
    asm volatile(
        "mma.sync.aligned.m16n8k16.row.col.f32.bf16.bf16.f32 "
        "{%0,%1,%2,%3}, {%4,%5,%6,%7}, {%8,%9}, {%0,%1,%2,%3};"
        : "+f"(d[0]), "+f"(d[1]), "+f"(d[2]), "+f"(d[3])
        : "r"(a[0]), "r"(a[1]), "r"(a[2]), "r"(a[3]), "r"(b[0]), "r"(b[1]));
}
__device__ __forceinline__ void ldsm4(uint32_t* r, const void* p) {
    uint32_t a = (uint32_t)__cvta_generic_to_shared(p);
    asm volatile("ldmatrix.sync.aligned.m8n8.x4.shared.b16 {%0,%1,%2,%3}, [%4];"
                 : "=r"(r[0]), "=r"(r[1]), "=r"(r[2]), "=r"(r[3]) : "r"(a));
}
__device__ __forceinline__ void ldsm2(uint32_t* r, const void* p) {
    uint32_t a = (uint32_t)__cvta_generic_to_shared(p);
    asm volatile("ldmatrix.sync.aligned.m8n8.x2.shared.b16 {%0,%1}, [%2];"
                 : "=r"(r[0]), "=r"(r[1]) : "r"(a));
}
__device__ __forceinline__ void ldsm2t(uint32_t* r, const void* p) {
    uint32_t a = (uint32_t)__cvta_generic_to_shared(p);
    asm volatile("ldmatrix.sync.aligned.m8n8.x2.trans.shared.b16 {%0,%1}, [%2];"
                 : "=r"(r[0]), "=r"(r[1]) : "r"(a));
}

// ---------------------------------------------------------------------------
// Kernel 1: per-head projection -> bf16 hi/lo splits in (N,H,S,D)
// ---------------------------------------------------------------------------
__global__ __launch_bounds__(256) void proj_kernel(
    const float* __restrict__ in, const float* __restrict__ W,
    const float* __restrict__ bias, int which, float scale)
{
    __shared__ float in_s[64 * 65];
    __shared__ float w_s[64 * 64];

    __nv_bfloat16* outh = (which == 0) ? g_vh : (which == 1) ? g_kh : g_qh;
    __nv_bfloat16* outl = (which == 0) ? g_vl : (which == 1) ? g_kl : g_ql;

    int t = threadIdx.x;
    int rowBase = blockIdx.x * 64;

    for (int i = t; i < 4096; i += 256) w_s[i] = W[i];
    for (int i = t; i < 4096; i += 256) {
        int r = i >> 6, k = i & 63;
        in_s[r * 65 + k] = in[(size_t)rowBase * 64 + i];
    }
    __syncthreads();

    int tr = t >> 4, tc = t & 15;
    int r0 = tr * 4, c0 = tc * 4;

    float acc[4][4];
    #pragma unroll
    for (int u = 0; u < 4; u++)
        #pragma unroll
        for (int v = 0; v < 4; v++) acc[u][v] = bias[c0 + v];

    #pragma unroll 8
    for (int k = 0; k < 64; k++) {
        float4 b = *(const float4*)&w_s[k * 64 + c0];
        float a[4];
        #pragma unroll
        for (int u = 0; u < 4; u++) a[u] = in_s[(r0 + u) * 65 + k];
        #pragma unroll
        for (int u = 0; u < 4; u++) {
            acc[u][0] += a[u] * b.x; acc[u][1] += a[u] * b.y;
            acc[u][2] += a[u] * b.z; acc[u][3] += a[u] * b.w;
        }
    }

    #pragma unroll
    for (int u = 0; u < 4; u++) {
        int row = rowBase + r0 + u;
        int n = row >> 15;
        int rem = row & 32767;
        int s = rem >> 4;
        int h = rem & 15;
        size_t base = (((size_t)(n * NHEADS + h)) * SLEN + s) * HDIM + c0;
        float v0 = acc[u][0] * scale, v1 = acc[u][1] * scale;
        float v2 = acc[u][2] * scale, v3 = acc[u][3] * scale;
        *(uint32_t*)&outh[base + 0] = pack_bf2(v0, v1);
        *(uint32_t*)&outh[base + 2] = pack_bf2(v2, v3);
        *(uint32_t*)&outl[base + 0] = pack_bf2(v0 - bf_round(v0), v1 - bf_round(v1));
        *(uint32_t*)&outl[base + 2] = pack_bf2(v2 - bf_round(v2), v3 - bf_round(v3));
    }
}

// ---------------------------------------------------------------------------
// Kernel 2: transpose + split Wo -> WoT hi/lo (e,k)
// ---------------------------------------------------------------------------
__global__ __launch_bounds__(256) void wo_convert(const float* __restrict__ Wo)
{
    __shared__ float ts[64 * 65];
    int t = threadIdx.x;
    int kb = blockIdx.x * 64, eb = blockIdx.y * 64;
    for (int i = t; i < 4096; i += 256) {
        int r = i >> 6, c = i & 63;
        ts[c * 65 + r] = Wo[(size_t)(kb + r) * EMB + eb + c];
    }
    __syncthreads();
    for (int i = t; i < 4096; i += 256) {
        int e = i >> 6, k = i & 63;
        float v = ts[e * 65 + k];
        size_t o = (size_t)(eb + e) * EMB + kb + k;
        g_woth[o] = __float2bfloat16(v);
        g_wotl[o] = __float2bfloat16(v - bf_round(v));
    }
}

// ---------------------------------------------------------------------------
// Kernel 3: register-resident flash attention via raw mma.sync.
// CTA = (qt, nh): 128 q-rows x full S; warp w owns rows [w*16, w*16+16).
// Scores never touch smem: C-frag -> exp -> A-frag identity -> PV.
// Smem = K/V hi/lo only (72KB). 2 syncs per KV tile.
// ---------------------------------------------------------------------------
#define LDH 72                 // bf16 row stride (144B: 8-row ldmatrix conflict-free)
#define TS 128                 // KV tile size

#define A_KH 0
#define A_KL (A_KH + TS * LDH * 2)     // 18432
#define A_VH (A_KL + TS * LDH * 2)     // 36864
#define A_VL (A_VH + TS * LDH * 2)     // 55296
#define ATTN_SMEM (A_VL + TS * LDH * 2)  // 73728 (72KB)

__global__ __launch_bounds__(256) void attn_flash(const float* __restrict__ mask)
{
    extern __shared__ char smem[];
    __nv_bfloat16* kh = (__nv_bfloat16*)(smem + A_KH);
    __nv_bfloat16* kl = (__nv_bfloat16*)(smem + A_KL);
    __nv_bfloat16* vh = (__nv_bfloat16*)(smem + A_VH);
    __nv_bfloat16* vl = (__nv_bfloat16*)(smem + A_VL);

    int t = threadIdx.x;
    int w = t >> 5;
    int lane = t & 31;
    int g = lane >> 2;          // group id (row within 8)
    int qd = lane & 3;          // thread-in-quad (col pair)
    int qt = blockIdx.x;        // 0..15
    int nh = blockIdx.y;        // 0..31

    // --- stage Q hi/lo into kh/kl area (dead after fragment load) ---
    {
        const __nv_bfloat16* gqh = g_qh + ((size_t)nh * SLEN + (size_t)qt * 128) * HDIM;
        const __nv_bfloat16* gql = g_ql + ((size_t)nh * SLEN + (size_t)qt * 128) * HDIM;
        for (int i = t; i < 1024; i += 256) {
            int r = i >> 3, c = i & 7;
            *(uint4*)(kh + r * LDH + c * 8) = *(const uint4*)(gqh + (size_t)r * 64 + c * 8);
            *(uint4*)(kl + r * LDH + c * 8) = *(const uint4*)(gql + (size_t)r * 64 + c * 8);
        }
    }
    __syncthreads();

    // --- Q fragments (A-operand, m16k16) hoisted for all KV tiles ---
    // ldmatrix.x4 lane addressing: row = w*16 + (lane&7) + ((lane>>3)&1)*8,
    //                              col = kf*16 + (lane>>4)*8
    uint32_t qfh[4][4], qfl[4][4];
    {
        int lr = (lane & 7) + ((lane >> 3) & 1) * 8;
        int lc = (lane >> 4) * 8;
        #pragma unroll
        for (int kf = 0; kf < 4; kf++) {
            ldsm4(qfh[kf], kh + (w * 16 + lr) * LDH + kf * 16 + lc);
            ldsm4(qfl[kf], kl + (w * 16 + lr) * LDH + kf * 16 + lc);
        }
    }
    __syncthreads();   // Q staging dead; K/V loads may overwrite

    float oacc[8][4];
    #pragma unroll
    for (int dn = 0; dn < 8; dn++)
        #pragma unroll
        for (int c = 0; c < 4; c++) oacc[dn][c] = 0.f;
    float lsum0 = 0.f, lsum1 = 0.f;   // rows w*16+g and w*16+g+8

    int r0 = qt * 128 + w * 16 + g;
    const float* mrow0 = mask + (size_t)r0 * SLEN + 2 * qd;
    const float* mrow1 = mask + (size_t)(r0 + 8) * SLEN + 2 * qd;

    // K b-frag addr (x2, lanes 0-15): row = nb*8 + (lane&7), col = kf*16 + ((lane&15)>>3)*8
    int k_lr = lane & 7;
    int k_lc = ((lane & 15) >> 3) * 8;
    // V b-frag addr (x2.trans, lanes 0-15): row = kb*16 + (lane&15), col = dn*8
    int v_lr = lane & 15;

    for (int kt = 0; kt < SLEN / TS; kt++) {
        // --- cooperative load K/V hi/lo tiles (128 x 64 bf16 each) ---
        {
            size_t gb = ((size_t)nh * SLEN + (size_t)kt * TS) * HDIM;
            for (int i = t; i < 1024; i += 256) {
                int r = i >> 3, c = i & 7;
                size_t gg = gb + (size_t)r * 64 + c * 8;
                int s = r * LDH + c * 8;
                *(uint4*)(kh + s) = *(const uint4*)(g_kh + gg);
                *(uint4*)(kl + s) = *(const uint4*)(g_kl + gg);
                *(uint4*)(vh + s) = *(const uint4*)(g_vh + gg);
                *(uint4*)(vl + s) = *(const uint4*)(g_vl + gg);
            }
        }
        __syncthreads();

        // --- per pair of n8 blocks: S (3-term), mask+exp, pack to P frags ---
        uint32_t pfh[8][4], pfl[8][4];
        #pragma unroll
        for (int p = 0; p < 8; p++) {
            float s0[4] = {0.f, 0.f, 0.f, 0.f};   // n-block 2p
            float s1[4] = {0.f, 0.f, 0.f, 0.f};   // n-block 2p+1
            #pragma unroll
            for (int kf = 0; kf < 4; kf++) {
                uint32_t bh0[2], bh1[2], bl0[2], bl1[2];
                const __nv_bfloat16* k0h = kh + ((2*p) * 8 + k_lr) * LDH + kf * 16 + k_lc;
                const __nv_bfloat16* k1h = kh + ((2*p+1) * 8 + k_lr) * LDH + kf * 16 + k_lc;
                const __nv_bfloat16* k0l = kl + ((2*p) * 8 + k_lr) * LDH + kf * 16 + k_lc;
                const __nv_bfloat16* k1l = kl + ((2*p+1) * 8 + k_lr) * LDH + kf * 16 + k_lc;
                ldsm2(bh0, k0h);
                ldsm2(bh1, k1h);
                mma16816(s0, qfh[kf], bh0);
                mma16816(s1, qfh[kf], bh1);
                mma16816(s0, qfl[kf], bh0);
                mma16816(s1, qfl[kf], bh1);
                ldsm2(bl0, k0l);
                ldsm2(bl1, k1l);
                mma16816(s0, qfh[kf], bl0);
                mma16816(s1, qfh[kf], bl1);
            }
            // mask + exp: c0,c1 -> row r0; c2,c3 -> row r0+8
            int col0 = kt * TS + (2*p) * 8;
            int col1 = kt * TS + (2*p+1) * 8;
            float2 ma = *(const float2*)(mrow0 + col0);
            float2 mb = *(const float2*)(mrow1 + col0);
            float2 mc = *(const float2*)(mrow0 + col1);
            float2 md = *(const float2*)(mrow1 + col1);
            float e0 = __expf(s0[0] * ma.x), e1 = __expf(s0[1] * ma.y);
            float e2 = __expf(s0[2] * mb.x), e3 = __expf(s0[3] * mb.y);
            float e4 = __expf(s1[0] * mc.x), e5 = __expf(s1[1] * mc.y);
            float e6 = __expf(s1[2] * md.x), e7 = __expf(s1[3] * md.y);
            lsum0 += (e0 + e1) + (e4 + e5);
            lsum1 += (e2 + e3) + (e6 + e7);
            // C->A identity: a0=pack(c0,c1)|nb=2p, a1=pack(c2,c3)|2p,
            //                a2=pack(c0,c1)|2p+1, a3=pack(c2,c3)|2p+1
            pfh[p][0] = pack_bf2(e0, e1);
            pfh[p][1] = pack_bf2(e2, e3);
            pfh[p][2] = pack_bf2(e4, e5);
            pfh[p][3] = pack_bf2(e6, e7);
            pfl[p][0] = pack_bf2(e0 - bf_round(e0), e1 - bf_round(e1));
            pfl[p][1] = pack_bf2(e2 - bf_round(e2), e3 - bf_round(e3));
            pfl[p][2] = pack_bf2(e4 - bf_round(e4), e5 - bf_round(e5));
            pfl[p][3] = pack_bf2(e6 - bf_round(e6), e7 - bf_round(e7));
        }

        // --- O += Ph.Vh + Ph.Vl + Pl.Vh ---
        #pragma unroll
        for (int kb = 0; kb < 8; kb++) {
            #pragma unroll
            for (int dn = 0; dn < 8; dn++) {
                uint32_t bh[2], bl[2];
                const __nv_bfloat16* vph = vh + (kb * 16 + v_lr) * LDH + dn * 8;
                ldsm2t(bh, vph);
                mma16816(oacc[dn], pfh[kb], bh);
                mma16816(oacc[dn], pfl[kb], bh);
                const __nv_bfloat16* vpl = vl + (kb * 16 + v_lr) * LDH + dn * 8;
                ldsm2t(bl, vpl);
                mma16816(oacc[dn], pfh[kb], bl);
            }
        }
        __syncthreads();   // before next tile overwrites K/V smem
    }

    // --- epilogue: quad-reduce lsum, normalize, split hi/lo, store ---
    lsum0 += __shfl_xor_sync(0xffffffffu, lsum0, 1);
    lsum0 += __shfl_xor_sync(0xffffffffu, lsum0, 2);
    lsum1 += __shfl_xor_sync(0xffffffffu, lsum1, 1);
    lsum1 += __shfl_xor_sync(0xffffffffu, lsum1, 2);
    float inv0 = 1.f / lsum0, inv1 = 1.f / lsum1;

    int nb_ = nh >> 4, h = nh & 15;
    size_t base0 = ((size_t)nb_ * SLEN + qt * 128 + w * 16 + g) * EMB + h * 64 + 2 * qd;
    size_t base1 = base0 + (size_t)8 * EMB;
    #pragma unroll
    for (int dn = 0; dn < 8; dn++) {
        int c = dn * 8;
        float o0 = oacc[dn][0] * inv0, o1 = oacc[dn][1] * inv0;
        float o2 = oacc[dn][2] * inv1, o3 = oacc[dn][3] * inv1;
        *(uint32_t*)&g_oh[base0 + c] = pack_bf2(o0, o1);
        *(uint32_t*)&g_ol[base0 + c] = pack_bf2(o0 - bf_round(o0), o1 - bf_round(o1));
        *(uint32_t*)&g_oh[base1 + c] = pack_bf2(o2, o3);
        *(uint32_t*)&g_ol[base1 + c] = pack_bf2(o2 - bf_round(o2), o3 - bf_round(o3));
    }
}

// ---------------------------------------------------------------------------
// Kernel 4: output projection out[m][e] = att[m][:] . WoT[e][:] + bo[e]
// (unchanged from the R12 1032us version)
// ---------------------------------------------------------------------------
#define LDS 68
#define P_AH 0
#define P_AL (P_AH + 128 * LDH * 2)
#define P_BH (P_AL + 128 * LDH * 2)
#define P_BL (P_BH + 64 * LDH * 2)
#define P_SF (P_BL + 64 * LDH * 2)
#define PROJ_SMEM (P_SF + 128 * LDS * 4)     // 90112

typedef wmma::fragment<wmma::matrix_a, 16, 16, 16, __nv_bfloat16, wmma::row_major> FragA;
typedef wmma::fragment<wmma::matrix_b, 16, 16, 16, __nv_bfloat16, wmma::col_major> FragBC;
typedef wmma::fragment<wmma::accumulator, 16, 16, 16, float> FragC;

__global__ __launch_bounds__(256) void outproj_wmma(
    const float* __restrict__ bo, float* __restrict__ out)
{
    extern __shared__ char smem[];
    __nv_bfloat16* ah = (__nv_bfloat16*)(smem + P_AH);
    __nv_bfloat16* al = (__nv_bfloat16*)(smem + P_AL);
    __nv_bfloat16* bh = (__nv_bfloat16*)(smem + P_BH);
    __nv_bfloat16* bl = (__nv_bfloat16*)(smem + P_BL);
    float*         sf = (float*)(smem + P_SF);

    int t = threadIdx.x;
    int w = t >> 5;
    int et = blockIdx.x;    // 0..15
    int mt = blockIdx.y;    // 0..31

    FragC oacc[4];
    #pragma unroll
    for (int n = 0; n < 4; n++) wmma::fill_fragment(oacc[n], 0.f);

    for (int kt = 0; kt < EMB / 64; kt++) {
        {
            const __nv_bfloat16* gah = g_oh + (size_t)(mt * 128) * EMB + kt * 64;
            const __nv_bfloat16* gal = g_ol + (size_t)(mt * 128) * EMB + kt * 64;
            for (int i = t; i < 1024; i += 256) {
                int r = i >> 3, c = i & 7;
                *(uint4*)(ah + r * LDH + c * 8) = *(const uint4*)(gah + (size_t)r * EMB + c * 8);
                *(uint4*)(al + r * LDH + c * 8) = *(const uint4*)(gal + (size_t)r * EMB + c * 8);
            }
            const __nv_bfloat16* gbh = g_woth + (size_t)(et * 64) * EMB + kt * 64;
            const __nv_bfloat16* gbl = g_wotl + (size_t)(et * 64) * EMB + kt * 64;
            for (int i = t; i < 512; i += 256) {
                int r = i >> 3, c = i & 7;
                *(uint4*)(bh + r * LDH + c * 8) = *(const uint4*)(gbh + (size_t)r * EMB + c * 8);
                *(uint4*)(bl + r * LDH + c * 8) = *(const uint4*)(gbl + (size_t)r * EMB + c * 8);
            }
        }
        __syncthreads();

        FragA aH[4], aL[4];
        #pragma unroll
        for (int kf = 0; kf < 4; kf++) {
            wmma::load_matrix_sync(aH[kf], ah + (w * 16) * LDH + kf * 16, LDH);
            wmma::load_matrix_sync(aL[kf], al + (w * 16) * LDH + kf * 16, LDH);
        }
        #pragma unroll
        for (int n = 0; n < 4; n++) {
            #pragma unroll
            for (int kf = 0; kf < 4; kf++) {
                FragBC bH, bL;
                wmma::load_matrix_sync(bH, bh + (n * 16) * LDH + kf * 16, LDH);
                wmma::mma_sync(oacc[n], aH[kf], bH, oacc[n]);
                wmma::mma_sync(oacc[n], aL[kf], bH, oacc[n]);
                wmma::load_matrix_sync(bL, bl + (n * 16) * LDH + kf * 16, LDH);
                wmma::mma_sync(oacc[n], aH[kf], bL, oacc[n]);
            }
        }
        __syncthreads();
    }

    #pragma unroll
    for (int n = 0; n < 4; n++)
        wmma::store_matrix_sync(sf + (w * 16) * LDS + n * 16, oacc[n], LDS, wmma::mem_row_major);
    __syncthreads();

    if (t < 128) {
        size_t m = (size_t)mt * 128 + t;
        float* dst = out + m * EMB + et * 64;
        const float* srow = sf + t * LDS;
        #pragma unroll
        for (int c4 = 0; c4 < 16; c4++) {
            float4 s = ((const float4*)srow)[c4];
            float4 bb = *(const float4*)&bo[et * 64 + c4 * 4];
            *(float4*)(dst + c4 * 4) = make_float4(s.x + bb.x, s.y + bb.y, s.z + bb.z, s.w + bb.w);
        }
    }
}

// ---------------------------------------------------------------------------
extern "C" void kernel_launch(void* const* d_in, const int* in_sizes, int n_in,
                              void* d_out, int out_size)
{
    const float* values  = (const float*)d_in[0];
    const float* keys    = (const float*)d_in[1];
    const float* queries = (const float*)d_in[2];
    const float* mask    = (const float*)d_in[3];
    const float* Wv = (const float*)d_in[4];
    const float* bv = (const float*)d_in[5];
    const float* Wk = (const float*)d_in[6];
    const float* bk = (const float*)d_in[7];
    const float* Wq = (const float*)d_in[8];
    const float* bq = (const float*)d_in[9];
    const float* Wo = (const float*)d_in[10];
    const float* bo = (const float*)d_in[11];
    float* out = (float*)d_out;

    cudaFuncSetAttribute(attn_flash, cudaFuncAttributeMaxDynamicSharedMemorySize, ATTN_SMEM);
    cudaFuncSetAttribute(outproj_wmma, cudaFuncAttributeMaxDynamicSharedMemorySize, PROJ_SMEM);

    proj_kernel<<<NROWS / 64, 256>>>(values,  Wv, bv, 0, 1.0f);
    proj_kernel<<<NROWS / 64, 256>>>(keys,    Wk, bk, 1, 1.0f);
    proj_kernel<<<NROWS / 64, 256>>>(queries, Wq, bq, 2, 0.03125f);   // fold 1/sqrt(EMB)
    wo_convert<<<dim3(16, 16), 256>>>(Wo);

    attn_flash<<<dim3(SLEN / 128, NH), 256, ATTN_SMEM>>>(mask);

    outproj_wmma<<<dim3(EMB / 64, NB * SLEN / 128), 256, PROJ_SMEM>>>(bo, out);
}

// round 15
// speedup vs baseline: 2.2511x; 1.1821x over previous
#include <cuda_runtime.h>
#include <cuda_bf16.h>
#include <mma.h>
#include <cstdint>
#include <math.h>

using namespace nvcuda;

#define NB 2
#define SLEN 2048
#define NHEADS 16
#define HDIM 64
#define EMB 1024
#define NH (NB * NHEADS)
#define NROWS (NB * SLEN * NHEADS)

// ---------------------------------------------------------------------------
// Global scratch (allocation-free rule: __device__ globals)
// ---------------------------------------------------------------------------
__device__ __align__(16) __nv_bfloat16 g_qh[(size_t)NH * SLEN * HDIM];
__device__ __align__(16) __nv_bfloat16 g_ql[(size_t)NH * SLEN * HDIM];
__device__ __align__(16) __nv_bfloat16 g_kh[(size_t)NH * SLEN * HDIM];
__device__ __align__(16) __nv_bfloat16 g_kl[(size_t)NH * SLEN * HDIM];
__device__ __align__(16) __nv_bfloat16 g_vh[(size_t)NH * SLEN * HDIM];
__device__ __align__(16) __nv_bfloat16 g_vl[(size_t)NH * SLEN * HDIM];
__device__ __align__(16) __nv_bfloat16 g_oh[(size_t)NB * SLEN * EMB];   // attn out hi
__device__ __align__(16) __nv_bfloat16 g_ol[(size_t)NB * SLEN * EMB];   // attn out lo
__device__ __align__(16) __nv_bfloat16 g_woth[(size_t)EMB * EMB];       // Wo^T hi (e,k)
__device__ __align__(16) __nv_bfloat16 g_wotl[(size_t)EMB * EMB];       // Wo^T lo (e,k)

__device__ __forceinline__ uint32_t pack_bf2(float a, float b) {
    __nv_bfloat16 x = __float2bfloat16(a), y = __float2bfloat16(b);
    return ((uint32_t)__bfloat16_as_ushort(y) << 16) | (uint32_t)__bfloat16_as_ushort(x);
}
__device__ __forceinline__ float bf_round(float a) {
    return __bfloat162float(__float2bfloat16(a));
}

// ---- raw tensor-core / async-copy primitives (sm_80+, no arch-suffix) ----
__device__ __forceinline__ void mma16816(float* d, const uint32_t* a, const uint32_t* b) {
    asm volatile(
        "mma.sync.aligned.m16n8k16.row.col.f32.bf16.bf16.f32 "
        "{%0,%1,%2,%3}, {%4,%5,%6,%7}, {%8,%9}, {%0,%1,%2,%3};"
        : "+f"(d[0]), "+f"(d[1]), "+f"(d[2]), "+f"(d[3])
        : "r"(a[0]), "r"(a[1]), "r"(a[2]), "r"(a[3]), "r"(b[0]), "r"(b[1]));
}
__device__ __forceinline__ void ldsm4(uint32_t* r, const void* p) {
    uint32_t a = (uint32_t)__cvta_generic_to_shared(p);
    asm volatile("ldmatrix.sync.aligned.m8n8.x4.shared.b16 {%0,%1,%2,%3}, [%4];"
                 : "=r"(r[0]), "=r"(r[1]), "=r"(r[2]), "=r"(r[3]) : "r"(a));
}
__device__ __forceinline__ void ldsm2(uint32_t* r, const void* p) {
    uint32_t a = (uint32_t)__cvta_generic_to_shared(p);
    asm volatile("ldmatrix.sync.aligned.m8n8.x2.shared.b16 {%0,%1}, [%2];"
                 : "=r"(r[0]), "=r"(r[1]) : "r"(a));
}
__device__ __forceinline__ void ldsm2t(uint32_t* r, const void* p) {
    uint32_t a = (uint32_t)__cvta_generic_to_shared(p);
    asm volatile("ldmatrix.sync.aligned.m8n8.x2.trans.shared.b16 {%0,%1}, [%2];"
                 : "=r"(r[0]), "=r"(r[1]) : "r"(a));
}
__device__ __forceinline__ void cp16(void* s, const void* g) {
    uint32_t sa = (uint32_t)__cvta_generic_to_shared(s);
    asm volatile("cp.async.cg.shared.global [%0], [%1], 16;" :: "r"(sa), "l"(g));
}
#define CP_COMMIT() asm volatile("cp.async.commit_group;" ::: "memory")
#define CP_WAIT0()  asm volatile("cp.async.wait_group 0;" ::: "memory")

// ---------------------------------------------------------------------------
// Kernel 1: per-head projection -> bf16 hi/lo splits in (N,H,S,D)
// ---------------------------------------------------------------------------
__global__ __launch_bounds__(256) void proj_kernel(
    const float* __restrict__ in, const float* __restrict__ W,
    const float* __restrict__ bias, int which, float scale)
{
    __shared__ float in_s[64 * 65];
    __shared__ float w_s[64 * 64];

    __nv_bfloat16* outh = (which == 0) ? g_vh : (which == 1) ? g_kh : g_qh;
    __nv_bfloat16* outl = (which == 0) ? g_vl : (which == 1) ? g_kl : g_ql;

    int t = threadIdx.x;
    int rowBase = blockIdx.x * 64;

    for (int i = t; i < 4096; i += 256) w_s[i] = W[i];
    for (int i = t; i < 4096; i += 256) {
        int r = i >> 6, k = i & 63;
        in_s[r * 65 + k] = in[(size_t)rowBase * 64 + i];
    }
    __syncthreads();

    int tr = t >> 4, tc = t & 15;
    int r0 = tr * 4, c0 = tc * 4;

    float acc[4][4];
    #pragma unroll
    for (int u = 0; u < 4; u++)
        #pragma unroll
        for (int v = 0; v < 4; v++) acc[u][v] = bias[c0 + v];

    #pragma unroll 8
    for (int k = 0; k < 64; k++) {
        float4 b = *(const float4*)&w_s[k * 64 + c0];
        float a[4];
        #pragma unroll
        for (int u = 0; u < 4; u++) a[u] = in_s[(r0 + u) * 65 + k];
        #pragma unroll
        for (int u = 0; u < 4; u++) {
            acc[u][0] += a[u] * b.x; acc[u][1] += a[u] * b.y;
            acc[u][2] += a[u] * b.z; acc[u][3] += a[u] * b.w;
        }
    }

    #pragma unroll
    for (int u = 0; u < 4; u++) {
        int row = rowBase + r0 + u;
        int n = row >> 15;
        int rem = row & 32767;
        int s = rem >> 4;
        int h = rem & 15;
        size_t base = (((size_t)(n * NHEADS + h)) * SLEN + s) * HDIM + c0;
        float v0 = acc[u][0] * scale, v1 = acc[u][1] * scale;
        float v2 = acc[u][2] * scale, v3 = acc[u][3] * scale;
        *(uint32_t*)&outh[base + 0] = pack_bf2(v0, v1);
        *(uint32_t*)&outh[base + 2] = pack_bf2(v2, v3);
        *(uint32_t*)&outl[base + 0] = pack_bf2(v0 - bf_round(v0), v1 - bf_round(v1));
        *(uint32_t*)&outl[base + 2] = pack_bf2(v2 - bf_round(v2), v3 - bf_round(v3));
    }
}

// ---------------------------------------------------------------------------
// Kernel 2: transpose + split Wo -> WoT hi/lo (e,k)
// ---------------------------------------------------------------------------
__global__ __launch_bounds__(256) void wo_convert(const float* __restrict__ Wo)
{
    __shared__ float ts[64 * 65];
    int t = threadIdx.x;
    int kb = blockIdx.x * 64, eb = blockIdx.y * 64;
    for (int i = t; i < 4096; i += 256) {
        int r = i >> 6, c = i & 63;
        ts[c * 65 + r] = Wo[(size_t)(kb + r) * EMB + eb + c];
    }
    __syncthreads();
    for (int i = t; i < 4096; i += 256) {
        int e = i >> 6, k = i & 63;
        float v = ts[e * 65 + k];
        size_t o = (size_t)(eb + e) * EMB + kb + k;
        g_woth[o] = __float2bfloat16(v);
        g_wotl[o] = __float2bfloat16(v - bf_round(v));
    }
}

// ---------------------------------------------------------------------------
// Kernel 3: register-resident flash attention, cp.async double-buffered K/V.
// CTA = (qt, nh): 128 q-rows x full S; warp w owns rows [w*16, w*16+16).
// Smem = 2 x 72KB K/V buffers. 2 syncs per KV tile; prefetch hides loads.
// ---------------------------------------------------------------------------
#define LDH 72                 // bf16 row stride (144B: 16B-aligned, ldmatrix-friendly)
#define TS 128                 // KV tile size

#define BUFB (4 * TS * LDH * 2)        // 73728 bytes per buffer
#define O_KH 0
#define O_KL (TS * LDH * 2)            // 18432
#define O_VH (2 * TS * LDH * 2)        // 36864
#define O_VL (3 * TS * LDH * 2)        // 55296
#define ATTN_SMEM (2 * BUFB)           // 147456 (144KB)

__global__ __launch_bounds__(256) void attn_flash(const float* __restrict__ mask)
{
    extern __shared__ char smem[];

    int t = threadIdx.x;
    int w = t >> 5;
    int lane = t & 31;
    int g = lane >> 2;
    int qd = lane & 3;
    int qt = blockIdx.x;        // 0..15
    int nh = blockIdx.y;        // 0..31

    // --- stage Q hi/lo into buf0 K area (dead after fragment load) ---
    {
        __nv_bfloat16* sqh = (__nv_bfloat16*)(smem + O_KH);
        __nv_bfloat16* sql = (__nv_bfloat16*)(smem + O_KL);
        const __nv_bfloat16* gqh = g_qh + ((size_t)nh * SLEN + (size_t)qt * 128) * HDIM;
        const __nv_bfloat16* gql = g_ql + ((size_t)nh * SLEN + (size_t)qt * 128) * HDIM;
        for (int i = t; i < 1024; i += 256) {
            int r = i >> 3, c = i & 7;
            *(uint4*)(sqh + r * LDH + c * 8) = *(const uint4*)(gqh + (size_t)r * 64 + c * 8);
            *(uint4*)(sql + r * LDH + c * 8) = *(const uint4*)(gql + (size_t)r * 64 + c * 8);
        }
    }
    __syncthreads();

    // --- Q fragments (A-operand, m16k16) hoisted for all KV tiles ---
    uint32_t qfh[4][4], qfl[4][4];
    {
        __nv_bfloat16* sqh = (__nv_bfloat16*)(smem + O_KH);
        __nv_bfloat16* sql = (__nv_bfloat16*)(smem + O_KL);
        int lr = (lane & 7) + ((lane >> 3) & 1) * 8;
        int lc = (lane >> 4) * 8;
        #pragma unroll
        for (int kf = 0; kf < 4; kf++) {
            ldsm4(qfh[kf], sqh + (w * 16 + lr) * LDH + kf * 16 + lc);
            ldsm4(qfl[kf], sql + (w * 16 + lr) * LDH + kf * 16 + lc);
        }
    }
    __syncthreads();   // Q staging dead; tile-0 prefetch may overwrite buf0

    size_t gb0 = (size_t)nh * SLEN * HDIM;

    // --- prologue: prefetch tile 0 into buf0 ---
    for (int i = t; i < 1024; i += 256) {
        int r = i >> 3, c = i & 7;
        size_t gg = gb0 + (size_t)r * 64 + c * 8;
        int s = r * LDH + c * 8;
        char* b0 = smem;
        cp16((__nv_bfloat16*)(b0 + O_KH) + s, g_kh + gg);
        cp16((__nv_bfloat16*)(b0 + O_KL) + s, g_kl + gg);
        cp16((__nv_bfloat16*)(b0 + O_VH) + s, g_vh + gg);
        cp16((__nv_bfloat16*)(b0 + O_VL) + s, g_vl + gg);
    }
    CP_COMMIT();

    float oacc[8][4];
    #pragma unroll
    for (int dn = 0; dn < 8; dn++)
        #pragma unroll
        for (int c = 0; c < 4; c++) oacc[dn][c] = 0.f;
    float lsum0 = 0.f, lsum1 = 0.f;

    int r0 = qt * 128 + w * 16 + g;
    const float* mrow0 = mask + (size_t)r0 * SLEN + 2 * qd;
    const float* mrow1 = mask + (size_t)(r0 + 8) * SLEN + 2 * qd;

    int k_lr = lane & 7;
    int k_lc = ((lane & 15) >> 3) * 8;
    int v_lr = lane & 15;

    for (int kt = 0; kt < SLEN / TS; kt++) {
        CP_WAIT0();
        __syncthreads();   // tile kt resident; prior compute done everywhere

        // --- prefetch tile kt+1 into the other buffer (overlaps compute) ---
        if (kt + 1 < SLEN / TS) {
            char* bn = smem + ((kt + 1) & 1) * BUFB;
            size_t gb = gb0 + (size_t)(kt + 1) * TS * HDIM;
            for (int i = t; i < 1024; i += 256) {
                int r = i >> 3, c = i & 7;
                size_t gg = gb + (size_t)r * 64 + c * 8;
                int s = r * LDH + c * 8;
                cp16((__nv_bfloat16*)(bn + O_KH) + s, g_kh + gg);
                cp16((__nv_bfloat16*)(bn + O_KL) + s, g_kl + gg);
                cp16((__nv_bfloat16*)(bn + O_VH) + s, g_vh + gg);
                cp16((__nv_bfloat16*)(bn + O_VL) + s, g_vl + gg);
            }
        }
        CP_COMMIT();

        char* bc = smem + (kt & 1) * BUFB;
        __nv_bfloat16* kh = (__nv_bfloat16*)(bc + O_KH);
        __nv_bfloat16* kl = (__nv_bfloat16*)(bc + O_KL);
        __nv_bfloat16* vh = (__nv_bfloat16*)(bc + O_VH);
        __nv_bfloat16* vl = (__nv_bfloat16*)(bc + O_VL);

        // --- per pair of n8 blocks: S (3-term), mask+exp, pack to P frags ---
        uint32_t pfh[8][4], pfl[8][4];
        #pragma unroll
        for (int p = 0; p < 8; p++) {
            float s0[4] = {0.f, 0.f, 0.f, 0.f};
            float s1[4] = {0.f, 0.f, 0.f, 0.f};
            #pragma unroll
            for (int kf = 0; kf < 4; kf++) {
                uint32_t bh0[2], bh1[2], bl0[2], bl1[2];
                const __nv_bfloat16* k0h = kh + ((2*p) * 8 + k_lr) * LDH + kf * 16 + k_lc;
                const __nv_bfloat16* k1h = kh + ((2*p+1) * 8 + k_lr) * LDH + kf * 16 + k_lc;
                const __nv_bfloat16* k0l = kl + ((2*p) * 8 + k_lr) * LDH + kf * 16 + k_lc;
                const __nv_bfloat16* k1l = kl + ((2*p+1) * 8 + k_lr) * LDH + kf * 16 + k_lc;
                ldsm2(bh0, k0h);
                ldsm2(bh1, k1h);
                mma16816(s0, qfh[kf], bh0);
                mma16816(s1, qfh[kf], bh1);
                mma16816(s0, qfl[kf], bh0);
                mma16816(s1, qfl[kf], bh1);
                ldsm2(bl0, k0l);
                ldsm2(bl1, k1l);
                mma16816(s0, qfh[kf], bl0);
                mma16816(s1, qfh[kf], bl1);
            }
            int col0 = kt * TS + (2*p) * 8;
            int col1 = kt * TS + (2*p+1) * 8;
            float2 ma = *(const float2*)(mrow0 + col0);
            float2 mb = *(const float2*)(mrow1 + col0);
            float2 mc = *(const float2*)(mrow0 + col1);
            float2 md = *(const float2*)(mrow1 + col1);
            float e0 = __expf(s0[0] * ma.x), e1 = __expf(s0[1] * ma.y);
            float e2 = __expf(s0[2] * mb.x), e3 = __expf(s0[3] * mb.y);
            float e4 = __expf(s1[0] * mc.x), e5 = __expf(s1[1] * mc.y);
            float e6 = __expf(s1[2] * md.x), e7 = __expf(s1[3] * md.y);
            lsum0 += (e0 + e1) + (e4 + e5);
            lsum1 += (e2 + e3) + (e6 + e7);
            pfh[p][0] = pack_bf2(e0, e1);
            pfh[p][1] = pack_bf2(e2, e3);
            pfh[p][2] = pack_bf2(e4, e5);
            pfh[p][3] = pack_bf2(e6, e7);
            pfl[p][0] = pack_bf2(e0 - bf_round(e0), e1 - bf_round(e1));
            pfl[p][1] = pack_bf2(e2 - bf_round(e2), e3 - bf_round(e3));
            pfl[p][2] = pack_bf2(e4 - bf_round(e4), e5 - bf_round(e5));
            pfl[p][3] = pack_bf2(e6 - bf_round(e6), e7 - bf_round(e7));
        }

        // --- O += Ph.Vh + Ph.Vl + Pl.Vh ---
        #pragma unroll
        for (int kb = 0; kb < 8; kb++) {
            #pragma unroll
            for (int dn = 0; dn < 8; dn++) {
                uint32_t bh[2], bl[2];
                ldsm2t(bh, vh + (kb * 16 + v_lr) * LDH + dn * 8);
                mma16816(oacc[dn], pfh[kb], bh);
                mma16816(oacc[dn], pfl[kb], bh);
                ldsm2t(bl, vl + (kb * 16 + v_lr) * LDH + dn * 8);
                mma16816(oacc[dn], pfh[kb], bl);
            }
        }
        __syncthreads();   // all warps done with buf[kt&1] before its reuse at kt+2
    }

    // --- epilogue: quad-reduce lsum, normalize, split hi/lo, store ---
    lsum0 += __shfl_xor_sync(0xffffffffu, lsum0, 1);
    lsum0 += __shfl_xor_sync(0xffffffffu, lsum0, 2);
    lsum1 += __shfl_xor_sync(0xffffffffu, lsum1, 1);
    lsum1 += __shfl_xor_sync(0xffffffffu, lsum1, 2);
    float inv0 = 1.f / lsum0, inv1 = 1.f / lsum1;

    int nb_ = nh >> 4, h = nh & 15;
    size_t base0 = ((size_t)nb_ * SLEN + qt * 128 + w * 16 + g) * EMB + h * 64 + 2 * qd;
    size_t base1 = base0 + (size_t)8 * EMB;
    #pragma unroll
    for (int dn = 0; dn < 8; dn++) {
        int c = dn * 8;
        float o0 = oacc[dn][0] * inv0, o1 = oacc[dn][1] * inv0;
        float o2 = oacc[dn][2] * inv1, o3 = oacc[dn][3] * inv1;
        *(uint32_t*)&g_oh[base0 + c] = pack_bf2(o0, o1);
        *(uint32_t*)&g_ol[base0 + c] = pack_bf2(o0 - bf_round(o0), o1 - bf_round(o1));
        *(uint32_t*)&g_oh[base1 + c] = pack_bf2(o2, o3);
        *(uint32_t*)&g_ol[base1 + c] = pack_bf2(o2 - bf_round(o2), o3 - bf_round(o3));
    }
}

// ---------------------------------------------------------------------------
// Kernel 4: output projection. CTA = (et, mt): 128 m-rows x 128 e-cols.
// Bias pre-loaded into accumulators; direct frag->gmem store (no sf buffer).
// ~80KB smem -> 2 CTAs/SM; kf-outer loop keeps live regs low.
// ---------------------------------------------------------------------------
#define P_AH 0
#define P_AL (P_AH + 128 * LDH * 2)      // 18432
#define P_BH (P_AL + 128 * LDH * 2)      // 36864
#define P_BL (P_BH + 128 * LDH * 2)      // 55296
#define P_BIAS (P_BL + 128 * LDH * 2)    // 73728: 16 x 132 f32
#define PROJ_SMEM (P_BIAS + 16 * 132 * 4)  // 82176

typedef wmma::fragment<wmma::matrix_a, 16, 16, 16, __nv_bfloat16, wmma::row_major> FragA;
typedef wmma::fragment<wmma::matrix_b, 16, 16, 16, __nv_bfloat16, wmma::col_major> FragBC;
typedef wmma::fragment<wmma::accumulator, 16, 16, 16, float> FragC;

__global__ __launch_bounds__(256, 2) void outproj_wmma(
    const float* __restrict__ bo, float* __restrict__ out)
{
    extern __shared__ char smem[];
    __nv_bfloat16* ah = (__nv_bfloat16*)(smem + P_AH);
    __nv_bfloat16* al = (__nv_bfloat16*)(smem + P_AL);
    __nv_bfloat16* bh = (__nv_bfloat16*)(smem + P_BH);
    __nv_bfloat16* bl = (__nv_bfloat16*)(smem + P_BL);
    float*         bias_s = (float*)(smem + P_BIAS);

    int t = threadIdx.x;
    int w = t >> 5;
    int et = blockIdx.x;    // 0..7   (128 e-cols per CTA)
    int mt = blockIdx.y;    // 0..31  (128 m-rows per CTA)

    // stage bias tile: 16 identical rows of bo[et*128 .. +128)
    for (int i = t; i < 16 * 128; i += 256) {
        int r = i >> 7, c = i & 127;
        bias_s[r * 132 + c] = bo[et * 128 + c];
    }
    __syncthreads();

    FragC oacc[8];
    #pragma unroll
    for (int n = 0; n < 8; n++)
        wmma::load_matrix_sync(oacc[n], bias_s + n * 16, 132, wmma::mem_row_major);
    __syncthreads();

    for (int kt = 0; kt < EMB / 64; kt++) {
        {
            const __nv_bfloat16* gah = g_oh + (size_t)(mt * 128) * EMB + kt * 64;
            const __nv_bfloat16* gal = g_ol + (size_t)(mt * 128) * EMB + kt * 64;
            const __nv_bfloat16* gbh = g_woth + (size_t)(et * 128) * EMB + kt * 64;
            const __nv_bfloat16* gbl = g_wotl + (size_t)(et * 128) * EMB + kt * 64;
            for (int i = t; i < 1024; i += 256) {
                int r = i >> 3, c = i & 7;
                size_t goff = (size_t)r * EMB + c * 8;
                int s = r * LDH + c * 8;
                *(uint4*)(ah + s) = *(const uint4*)(gah + goff);
                *(uint4*)(al + s) = *(const uint4*)(gal + goff);
                *(uint4*)(bh + s) = *(const uint4*)(gbh + goff);
                *(uint4*)(bl + s) = *(const uint4*)(gbl + goff);
            }
        }
        __syncthreads();

        // kf-outer: only 2 A-frags live at a time (keeps regs < 128)
        #pragma unroll
        for (int kf = 0; kf < 4; kf++) {
            FragA aH, aL;
            wmma::load_matrix_sync(aH, ah + (w * 16) * LDH + kf * 16, LDH);
            wmma::load_matrix_sync(aL, al + (w * 16) * LDH + kf * 16, LDH);
            #pragma unroll
            for (int n = 0; n < 8; n++) {
                FragBC bH, bL;
                wmma::load_matrix_sync(bH, bh + (n * 16) * LDH + kf * 16, LDH);
                wmma::mma_sync(oacc[n], aH, bH, oacc[n]);
                wmma::mma_sync(oacc[n], aL, bH, oacc[n]);
                wmma::load_matrix_sync(bL, bl + (n * 16) * LDH + kf * 16, LDH);
                wmma::mma_sync(oacc[n], aH, bL, oacc[n]);
            }
        }
        __syncthreads();
    }

    // direct store to gmem (fp32 out, ldm = EMB)
    float* dst = out + (size_t)(mt * 128 + w * 16) * EMB + et * 128;
    #pragma unroll
    for (int n = 0; n < 8; n++)
        wmma::store_matrix_sync(dst + n * 16, oacc[n], EMB, wmma::mem_row_major);
}

// ---------------------------------------------------------------------------
extern "C" void kernel_launch(void* const* d_in, const int* in_sizes, int n_in,
                              void* d_out, int out_size)
{
    const float* values  = (const float*)d_in[0];
    const float* keys    = (const float*)d_in[1];
    const float* queries = (const float*)d_in[2];
    const float* mask    = (const float*)d_in[3];
    const float* Wv = (const float*)d_in[4];
    const float* bv = (const float*)d_in[5];
    const float* Wk = (const float*)d_in[6];
    const float* bk = (const float*)d_in[7];
    const float* Wq = (const float*)d_in[8];
    const float* bq = (const float*)d_in[9];
    const float* Wo = (const float*)d_in[10];
    const float* bo = (const float*)d_in[11];
    float* out = (float*)d_out;

    cudaFuncSetAttribute(attn_flash, cudaFuncAttributeMaxDynamicSharedMemorySize, ATTN_SMEM);
    cudaFuncSetAttribute(outproj_wmma, cudaFuncAttributeMaxDynamicSharedMemorySize, PROJ_SMEM);

    proj_kernel<<<NROWS / 64, 256>>>(values,  Wv, bv, 0, 1.0f);
    proj_kernel<<<NROWS / 64, 256>>>(keys,    Wk, bk, 1, 1.0f);
    proj_kernel<<<NROWS / 64, 256>>>(queries, Wq, bq, 2, 0.03125f);   // fold 1/sqrt(EMB)
    wo_convert<<<dim3(16, 16), 256>>>(Wo);

    attn_flash<<<dim3(SLEN / 128, NH), 256, ATTN_SMEM>>>(mask);

    outproj_wmma<<<dim3(EMB / 128, NB * SLEN / 128), 256, PROJ_SMEM>>>(bo, out);
}

// round 16
// speedup vs baseline: 2.2592x; 1.0036x over previous
#include <cuda_runtime.h>
#include <cuda_bf16.h>
#include <mma.h>
#include <cstdint>
#include <math.h>

using namespace nvcuda;

#define NB 2
#define SLEN 2048
#define NHEADS 16
#define HDIM 64
#define EMB 1024
#define NH (NB * NHEADS)
#define NROWS (NB * SLEN * NHEADS)

// ---------------------------------------------------------------------------
// Global scratch (allocation-free rule: __device__ globals)
// ---------------------------------------------------------------------------
__device__ __align__(16) __nv_bfloat16 g_qh[(size_t)NH * SLEN * HDIM];
__device__ __align__(16) __nv_bfloat16 g_ql[(size_t)NH * SLEN * HDIM];
__device__ __align__(16) __nv_bfloat16 g_kh[(size_t)NH * SLEN * HDIM];
__device__ __align__(16) __nv_bfloat16 g_kl[(size_t)NH * SLEN * HDIM];
__device__ __align__(16) __nv_bfloat16 g_vh[(size_t)NH * SLEN * HDIM];
__device__ __align__(16) __nv_bfloat16 g_vl[(size_t)NH * SLEN * HDIM];
__device__ __align__(16) __nv_bfloat16 g_oh[(size_t)NB * SLEN * EMB];   // attn out hi
__device__ __align__(16) __nv_bfloat16 g_ol[(size_t)NB * SLEN * EMB];   // attn out lo
__device__ __align__(16) __nv_bfloat16 g_woth[(size_t)EMB * EMB];       // Wo^T hi (e,k)
__device__ __align__(16) __nv_bfloat16 g_wotl[(size_t)EMB * EMB];       // Wo^T lo (e,k)

__device__ __forceinline__ uint32_t pack_bf2(float a, float b) {
    __nv_bfloat16 x = __float2bfloat16(a), y = __float2bfloat16(b);
    return ((uint32_t)__bfloat16_as_ushort(y) << 16) | (uint32_t)__bfloat16_as_ushort(x);
}
__device__ __forceinline__ float bf_round(float a) {
    return __bfloat162float(__float2bfloat16(a));
}

// ---- raw tensor-core / async-copy primitives (sm_80+, no arch-suffix) ----
__device__ __forceinline__ void mma16816(float* d, const uint32_t* a, const uint32_t* b) {
    asm volatile(
        "mma.sync.aligned.m16n8k16.row.col.f32.bf16.bf16.f32 "
        "{%0,%1,%2,%3}, {%4,%5,%6,%7}, {%8,%9}, {%0,%1,%2,%3};"
        : "+f"(d[0]), "+f"(d[1]), "+f"(d[2]), "+f"(d[3])
        : "r"(a[0]), "r"(a[1]), "r"(a[2]), "r"(a[3]), "r"(b[0]), "r"(b[1]));
}
__device__ __forceinline__ void ldsm4(uint32_t* r, const void* p) {
    uint32_t a = (uint32_t)__cvta_generic_to_shared(p);
    asm volatile("ldmatrix.sync.aligned.m8n8.x4.shared.b16 {%0,%1,%2,%3}, [%4];"
                 : "=r"(r[0]), "=r"(r[1]), "=r"(r[2]), "=r"(r[3]) : "r"(a));
}
__device__ __forceinline__ void ldsm4t(uint32_t* r, const void* p) {
    uint32_t a = (uint32_t)__cvta_generic_to_shared(p);
    asm volatile("ldmatrix.sync.aligned.m8n8.x4.trans.shared.b16 {%0,%1,%2,%3}, [%4];"
                 : "=r"(r[0]), "=r"(r[1]), "=r"(r[2]), "=r"(r[3]) : "r"(a));
}
__device__ __forceinline__ void cp16(void* s, const void* g) {
    uint32_t sa = (uint32_t)__cvta_generic_to_shared(s);
    asm volatile("cp.async.cg.shared.global [%0], [%1], 16;" :: "r"(sa), "l"(g));
}
#define CP_COMMIT() asm volatile("cp.async.commit_group;" ::: "memory")
#define CP_WAIT0()  asm volatile("cp.async.wait_group 0;" ::: "memory")

// ---------------------------------------------------------------------------
// Kernel 1: per-head projection -> bf16 hi/lo splits in (N,H,S,D)
// ---------------------------------------------------------------------------
__global__ __launch_bounds__(256) void proj_kernel(
    const float* __restrict__ in, const float* __restrict__ W,
    const float* __restrict__ bias, int which, float scale)
{
    __shared__ float in_s[64 * 65];
    __shared__ float w_s[64 * 64];

    __nv_bfloat16* outh = (which == 0) ? g_vh : (which == 1) ? g_kh : g_qh;
    __nv_bfloat16* outl = (which == 0) ? g_vl : (which == 1) ? g_kl : g_ql;

    int t = threadIdx.x;
    int rowBase = blockIdx.x * 64;

    for (int i = t; i < 4096; i += 256) w_s[i] = W[i];
    for (int i = t; i < 4096; i += 256) {
        int r = i >> 6, k = i & 63;
        in_s[r * 65 + k] = in[(size_t)rowBase * 64 + i];
    }
    __syncthreads();

    int tr = t >> 4, tc = t & 15;
    int r0 = tr * 4, c0 = tc * 4;

    float acc[4][4];
    #pragma unroll
    for (int u = 0; u < 4; u++)
        #pragma unroll
        for (int v = 0; v < 4; v++) acc[u][v] = bias[c0 + v];

    #pragma unroll 8
    for (int k = 0; k < 64; k++) {
        float4 b = *(const float4*)&w_s[k * 64 + c0];
        float a[4];
        #pragma unroll
        for (int u = 0; u < 4; u++) a[u] = in_s[(r0 + u) * 65 + k];
        #pragma unroll
        for (int u = 0; u < 4; u++) {
            acc[u][0] += a[u] * b.x; acc[u][1] += a[u] * b.y;
            acc[u][2] += a[u] * b.z; acc[u][3] += a[u] * b.w;
        }
    }

    #pragma unroll
    for (int u = 0; u < 4; u++) {
        int row = rowBase + r0 + u;
        int n = row >> 15;
        int rem = row & 32767;
        int s = rem >> 4;
        int h = rem & 15;
        size_t base = (((size_t)(n * NHEADS + h)) * SLEN + s) * HDIM + c0;
        float v0 = acc[u][0] * scale, v1 = acc[u][1] * scale;
        float v2 = acc[u][2] * scale, v3 = acc[u][3] * scale;
        *(uint32_t*)&outh[base + 0] = pack_bf2(v0, v1);
        *(uint32_t*)&outh[base + 2] = pack_bf2(v2, v3);
        *(uint32_t*)&outl[base + 0] = pack_bf2(v0 - bf_round(v0), v1 - bf_round(v1));
        *(uint32_t*)&outl[base + 2] = pack_bf2(v2 - bf_round(v2), v3 - bf_round(v3));
    }
}

// ---------------------------------------------------------------------------
// Kernel 2: transpose + split Wo -> WoT hi/lo (e,k)
// ---------------------------------------------------------------------------
__global__ __launch_bounds__(256) void wo_convert(const float* __restrict__ Wo)
{
    __shared__ float ts[64 * 65];
    int t = threadIdx.x;
    int kb = blockIdx.x * 64, eb = blockIdx.y * 64;
    for (int i = t; i < 4096; i += 256) {
        int r = i >> 6, c = i & 63;
        ts[c * 65 + r] = Wo[(size_t)(kb + r) * EMB + eb + c];
    }
    __syncthreads();
    for (int i = t; i < 4096; i += 256) {
        int e = i >> 6, k = i & 63;
        float v = ts[e * 65 + k];
        size_t o = (size_t)(eb + e) * EMB + kb + k;
        g_woth[o] = __float2bfloat16(v);
        g_wotl[o] = __float2bfloat16(v - bf_round(v));
    }
}

// ---------------------------------------------------------------------------
// Kernel 3: register-resident flash attention, cp.async double-buffered K/V,
// ldmatrix.x4 consolidated loads (half the LDSM issue count of R15).
// CTA = (qt, nh): 128 q-rows x full S; warp w owns rows [w*16, w*16+16).
// ---------------------------------------------------------------------------
#define LDH 72                 // bf16 row stride (144B)
#define TS 128                 // KV tile size

#define BUFB (4 * TS * LDH * 2)        // 73728 bytes per buffer
#define O_KH 0
#define O_KL (TS * LDH * 2)            // 18432
#define O_VH (2 * TS * LDH * 2)        // 36864
#define O_VL (3 * TS * LDH * 2)        // 55296
#define ATTN_SMEM (2 * BUFB)           // 147456 (144KB)

__global__ __launch_bounds__(256) void attn_flash(const float* __restrict__ mask)
{
    extern __shared__ char smem[];

    int t = threadIdx.x;
    int w = t >> 5;
    int lane = t & 31;
    int g = lane >> 2;
    int qd = lane & 3;
    int qt = blockIdx.x;        // 0..15
    int nh = blockIdx.y;        // 0..31

    // --- stage Q hi/lo into buf0 K area (dead after fragment load) ---
    {
        __nv_bfloat16* sqh = (__nv_bfloat16*)(smem + O_KH);
        __nv_bfloat16* sql = (__nv_bfloat16*)(smem + O_KL);
        const __nv_bfloat16* gqh = g_qh + ((size_t)nh * SLEN + (size_t)qt * 128) * HDIM;
        const __nv_bfloat16* gql = g_ql + ((size_t)nh * SLEN + (size_t)qt * 128) * HDIM;
        for (int i = t; i < 1024; i += 256) {
            int r = i >> 3, c = i & 7;
            *(uint4*)(sqh + r * LDH + c * 8) = *(const uint4*)(gqh + (size_t)r * 64 + c * 8);
            *(uint4*)(sql + r * LDH + c * 8) = *(const uint4*)(gql + (size_t)r * 64 + c * 8);
        }
    }
    __syncthreads();

    // --- Q fragments (A-operand, m16k16) hoisted for all KV tiles ---
    uint32_t qfh[4][4], qfl[4][4];
    {
        __nv_bfloat16* sqh = (__nv_bfloat16*)(smem + O_KH);
        __nv_bfloat16* sql = (__nv_bfloat16*)(smem + O_KL);
        int lr = (lane & 7) + ((lane >> 3) & 1) * 8;
        int lc = (lane >> 4) * 8;
        #pragma unroll
        for (int kf = 0; kf < 4; kf++) {
            ldsm4(qfh[kf], sqh + (w * 16 + lr) * LDH + kf * 16 + lc);
            ldsm4(qfl[kf], sql + (w * 16 + lr) * LDH + kf * 16 + lc);
        }
    }
    __syncthreads();   // Q staging dead; tile-0 prefetch may overwrite buf0

    size_t gb0 = (size_t)nh * SLEN * HDIM;

    // --- prologue: prefetch tile 0 into buf0 ---
    for (int i = t; i < 1024; i += 256) {
        int r = i >> 3, c = i & 7;
        size_t gg = gb0 + (size_t)r * 64 + c * 8;
        int s = r * LDH + c * 8;
        char* b0 = smem;
        cp16((__nv_bfloat16*)(b0 + O_KH) + s, g_kh + gg);
        cp16((__nv_bfloat16*)(b0 + O_KL) + s, g_kl + gg);
        cp16((__nv_bfloat16*)(b0 + O_VH) + s, g_vh + gg);
        cp16((__nv_bfloat16*)(b0 + O_VL) + s, g_vl + gg);
    }
    CP_COMMIT();

    float oacc[8][4];
    #pragma unroll
    for (int dn = 0; dn < 8; dn++)
        #pragma unroll
        for (int c = 0; c < 4; c++) oacc[dn][c] = 0.f;
    float lsum0 = 0.f, lsum1 = 0.f;

    int r0 = qt * 128 + w * 16 + g;
    const float* mrow0 = mask + (size_t)r0 * SLEN + 2 * qd;
    const float* mrow1 = mask + (size_t)(r0 + 8) * SLEN + 2 * qd;

    // x4 K-load lane map: row = 2p*8 + (lane>>4)*8 + (lane&7), col = kf*16 + ((lane>>3)&1)*8
    //   -> regs {b(2p)[0], b(2p)[1], b(2p+1)[0], b(2p+1)[1]}
    int k4_r = ((lane >> 4) & 1) * 8 + (lane & 7);
    int k4_c = ((lane >> 3) & 1) * 8;
    // x4t V-load lane map: row = kb*16 + (lane&15), col = (2*dnp + (lane>>4))*8
    //   -> regs {b(dn)[0], b(dn)[1], b(dn+1)[0], b(dn+1)[1]}
    int v4_r = lane & 15;
    int v4_c = (lane >> 4) * 8;

    for (int kt = 0; kt < SLEN / TS; kt++) {
        CP_WAIT0();
        __syncthreads();   // tile kt resident; prior compute done everywhere

        // --- prefetch tile kt+1 into the other buffer (overlaps compute) ---
        if (kt + 1 < SLEN / TS) {
            char* bn = smem + ((kt + 1) & 1) * BUFB;
            size_t gb = gb0 + (size_t)(kt + 1) * TS * HDIM;
            for (int i = t; i < 1024; i += 256) {
                int r = i >> 3, c = i & 7;
                size_t gg = gb + (size_t)r * 64 + c * 8;
                int s = r * LDH + c * 8;
                cp16((__nv_bfloat16*)(bn + O_KH) + s, g_kh + gg);
                cp16((__nv_bfloat16*)(bn + O_KL) + s, g_kl + gg);
                cp16((__nv_bfloat16*)(bn + O_VH) + s, g_vh + gg);
                cp16((__nv_bfloat16*)(bn + O_VL) + s, g_vl + gg);
            }
        }
        CP_COMMIT();

        char* bc = smem + (kt & 1) * BUFB;
        __nv_bfloat16* kh = (__nv_bfloat16*)(bc + O_KH);
        __nv_bfloat16* kl = (__nv_bfloat16*)(bc + O_KL);
        __nv_bfloat16* vh = (__nv_bfloat16*)(bc + O_VH);
        __nv_bfloat16* vl = (__nv_bfloat16*)(bc + O_VL);

        // --- per pair of n8 blocks: S (3-term), mask+exp, pack to P frags ---
        uint32_t pfh[8][4], pfl[8][4];
        #pragma unroll
        for (int p = 0; p < 8; p++) {
            float s0[4] = {0.f, 0.f, 0.f, 0.f};
            float s1[4] = {0.f, 0.f, 0.f, 0.f};
            #pragma unroll
            for (int kf = 0; kf < 4; kf++) {
                uint32_t bh[4], bl[4];
                ldsm4(bh, kh + (2 * p * 8 + k4_r) * LDH + kf * 16 + k4_c);
                mma16816(s0, qfh[kf], bh + 0);
                mma16816(s1, qfh[kf], bh + 2);
                mma16816(s0, qfl[kf], bh + 0);
                mma16816(s1, qfl[kf], bh + 2);
                ldsm4(bl, kl + (2 * p * 8 + k4_r) * LDH + kf * 16 + k4_c);
                mma16816(s0, qfh[kf], bl + 0);
                mma16816(s1, qfh[kf], bl + 2);
            }
            int col0 = kt * TS + (2*p) * 8;
            int col1 = kt * TS + (2*p+1) * 8;
            float2 ma = *(const float2*)(mrow0 + col0);
            float2 mb = *(const float2*)(mrow1 + col0);
            float2 mc = *(const float2*)(mrow0 + col1);
            float2 md = *(const float2*)(mrow1 + col1);
            float e0 = __expf(s0[0] * ma.x), e1 = __expf(s0[1] * ma.y);
            float e2 = __expf(s0[2] * mb.x), e3 = __expf(s0[3] * mb.y);
            float e4 = __expf(s1[0] * mc.x), e5 = __expf(s1[1] * mc.y);
            float e6 = __expf(s1[2] * md.x), e7 = __expf(s1[3] * md.y);
            lsum0 += (e0 + e1) + (e4 + e5);
            lsum1 += (e2 + e3) + (e6 + e7);
            pfh[p][0] = pack_bf2(e0, e1);
            pfh[p][1] = pack_bf2(e2, e3);
            pfh[p][2] = pack_bf2(e4, e5);
            pfh[p][3] = pack_bf2(e6, e7);
            pfl[p][0] = pack_bf2(e0 - bf_round(e0), e1 - bf_round(e1));
            pfl[p][1] = pack_bf2(e2 - bf_round(e2), e3 - bf_round(e3));
            pfl[p][2] = pack_bf2(e4 - bf_round(e4), e5 - bf_round(e5));
            pfl[p][3] = pack_bf2(e6 - bf_round(e6), e7 - bf_round(e7));
        }

        // --- O += Ph.Vh + Ph.Vl + Pl.Vh  (x4t loads: two d-columns per LDSM) ---
        #pragma unroll
        for (int kb = 0; kb < 8; kb++) {
            #pragma unroll
            for (int dnp = 0; dnp < 4; dnp++) {
                uint32_t bh[4], bl[4];
                ldsm4t(bh, vh + (kb * 16 + v4_r) * LDH + 2 * dnp * 8 + v4_c);
                mma16816(oacc[2*dnp],   pfh[kb], bh + 0);
                mma16816(oacc[2*dnp],   pfl[kb], bh + 0);
                mma16816(oacc[2*dnp+1], pfh[kb], bh + 2);
                mma16816(oacc[2*dnp+1], pfl[kb], bh + 2);
                ldsm4t(bl, vl + (kb * 16 + v4_r) * LDH + 2 * dnp * 8 + v4_c);
                mma16816(oacc[2*dnp],   pfh[kb], bl + 0);
                mma16816(oacc[2*dnp+1], pfh[kb], bl + 2);
            }
        }
        __syncthreads();   // all warps done with buf[kt&1] before its reuse at kt+2
    }

    // --- epilogue: quad-reduce lsum, normalize, split hi/lo, store ---
    lsum0 += __shfl_xor_sync(0xffffffffu, lsum0, 1);
    lsum0 += __shfl_xor_sync(0xffffffffu, lsum0, 2);
    lsum1 += __shfl_xor_sync(0xffffffffu, lsum1, 1);
    lsum1 += __shfl_xor_sync(0xffffffffu, lsum1, 2);
    float inv0 = 1.f / lsum0, inv1 = 1.f / lsum1;

    int nb_ = nh >> 4, h = nh & 15;
    size_t base0 = ((size_t)nb_ * SLEN + qt * 128 + w * 16 + g) * EMB + h * 64 + 2 * qd;
    size_t base1 = base0 + (size_t)8 * EMB;
    #pragma unroll
    for (int dn = 0; dn < 8; dn++) {
        int c = dn * 8;
        float o0 = oacc[dn][0] * inv0, o1 = oacc[dn][1] * inv0;
        float o2 = oacc[dn][2] * inv1, o3 = oacc[dn][3] * inv1;
        *(uint32_t*)&g_oh[base0 + c] = pack_bf2(o0, o1);
        *(uint32_t*)&g_ol[base0 + c] = pack_bf2(o0 - bf_round(o0), o1 - bf_round(o1));
        *(uint32_t*)&g_oh[base1 + c] = pack_bf2(o2, o3);
        *(uint32_t*)&g_ol[base1 + c] = pack_bf2(o2 - bf_round(o2), o3 - bf_round(o3));
    }
}

// ---------------------------------------------------------------------------
// Kernel 4: output projection. CTA = (et, mt): 128 m-rows x 128 e-cols.
// Bias in accumulators; direct frag->gmem store; cp.async tile loads.
// ~80KB smem -> 2 CTAs/SM (co-resident CTA hides load latency).
// ---------------------------------------------------------------------------
#define P_AH 0
#define P_AL (P_AH + 128 * LDH * 2)      // 18432
#define P_BH (P_AL + 128 * LDH * 2)      // 36864
#define P_BL (P_BH + 128 * LDH * 2)      // 55296
#define P_BIAS (P_BL + 128 * LDH * 2)    // 73728: 16 x 132 f32
#define PROJ_SMEM (P_BIAS + 16 * 132 * 4)  // 82176

typedef wmma::fragment<wmma::matrix_a, 16, 16, 16, __nv_bfloat16, wmma::row_major> FragA;
typedef wmma::fragment<wmma::matrix_b, 16, 16, 16, __nv_bfloat16, wmma::col_major> FragBC;
typedef wmma::fragment<wmma::accumulator, 16, 16, 16, float> FragC;

__global__ __launch_bounds__(256, 2) void outproj_wmma(
    const float* __restrict__ bo, float* __restrict__ out)
{
    extern __shared__ char smem[];
    __nv_bfloat16* ah = (__nv_bfloat16*)(smem + P_AH);
    __nv_bfloat16* al = (__nv_bfloat16*)(smem + P_AL);
    __nv_bfloat16* bh = (__nv_bfloat16*)(smem + P_BH);
    __nv_bfloat16* bl = (__nv_bfloat16*)(smem + P_BL);
    float*         bias_s = (float*)(smem + P_BIAS);

    int t = threadIdx.x;
    int w = t >> 5;
    int et = blockIdx.x;    // 0..7   (128 e-cols per CTA)
    int mt = blockIdx.y;    // 0..31  (128 m-rows per CTA)

    // stage bias tile: 16 identical rows of bo[et*128 .. +128)
    for (int i = t; i < 16 * 128; i += 256) {
        int r = i >> 7, c = i & 127;
        bias_s[r * 132 + c] = bo[et * 128 + c];
    }
    __syncthreads();

    FragC oacc[8];
    #pragma unroll
    for (int n = 0; n < 8; n++)
        wmma::load_matrix_sync(oacc[n], bias_s + n * 16, 132, wmma::mem_row_major);
    __syncthreads();

    for (int kt = 0; kt < EMB / 64; kt++) {
        {
            const __nv_bfloat16* gah = g_oh + (size_t)(mt * 128) * EMB + kt * 64;
            const __nv_bfloat16* gal = g_ol + (size_t)(mt * 128) * EMB + kt * 64;
            const __nv_bfloat16* gbh = g_woth + (size_t)(et * 128) * EMB + kt * 64;
            const __nv_bfloat16* gbl = g_wotl + (size_t)(et * 128) * EMB + kt * 64;
            for (int i = t; i < 1024; i += 256) {
                int r = i >> 3, c = i & 7;
                size_t goff = (size_t)r * EMB + c * 8;
                int s = r * LDH + c * 8;
                cp16(ah + s, gah + goff);
                cp16(al + s, gal + goff);
                cp16(bh + s, gbh + goff);
                cp16(bl + s, gbl + goff);
            }
        }
        CP_COMMIT();
        CP_WAIT0();
        __syncthreads();

        // kf-outer: only 2 A-frags live at a time (keeps regs < 128)
        #pragma unroll
        for (int kf = 0; kf < 4; kf++) {
            FragA aH, aL;
            wmma::load_matrix_sync(aH, ah + (w * 16) * LDH + kf * 16, LDH);
            wmma::load_matrix_sync(aL, al + (w * 16) * LDH + kf * 16, LDH);
            #pragma unroll
            for (int n = 0; n < 8; n++) {
                FragBC bH, bL;
                wmma::load_matrix_sync(bH, bh + (n * 16) * LDH + kf * 16, LDH);
                wmma::mma_sync(oacc[n], aH, bH, oacc[n]);
                wmma::mma_sync(oacc[n], aL, bH, oacc[n]);
                wmma::load_matrix_sync(bL, bl + (n * 16) * LDH + kf * 16, LDH);
                wmma::mma_sync(oacc[n], aH, bL, oacc[n]);
            }
        }
        __syncthreads();
    }

    // direct store to gmem (fp32 out, ldm = EMB)
    float* dst = out + (size_t)(mt * 128 + w * 16) * EMB + et * 128;
    #pragma unroll
    for (int n = 0; n < 8; n++)
        wmma::store_matrix_sync(dst + n * 16, oacc[n], EMB, wmma::mem_row_major);
}

// ---------------------------------------------------------------------------
extern "C" void kernel_launch(void* const* d_in, const int* in_sizes, int n_in,
                              void* d_out, int out_size)
{
    const float* values  = (const float*)d_in[0];
    const float* keys    = (const float*)d_in[1];
    const float* queries = (const float*)d_in[2];
    const float* mask    = (const float*)d_in[3];
    const float* Wv = (const float*)d_in[4];
    const float* bv = (const float*)d_in[5];
    const float* Wk = (const float*)d_in[6];
    const float* bk = (const float*)d_in[7];
    const float* Wq = (const float*)d_in[8];
    const float* bq = (const float*)d_in[9];
    const float* Wo = (const float*)d_in[10];
    const float* bo = (const float*)d_in[11];
    float* out = (float*)d_out;

    cudaFuncSetAttribute(attn_flash, cudaFuncAttributeMaxDynamicSharedMemorySize, ATTN_SMEM);
    cudaFuncSetAttribute(outproj_wmma, cudaFuncAttributeMaxDynamicSharedMemorySize, PROJ_SMEM);

    proj_kernel<<<NROWS / 64, 256>>>(values,  Wv, bv, 0, 1.0f);
    proj_kernel<<<NROWS / 64, 256>>>(keys,    Wk, bk, 1, 1.0f);
    proj_kernel<<<NROWS / 64, 256>>>(queries, Wq, bq, 2, 0.03125f);   // fold 1/sqrt(EMB)
    wo_convert<<<dim3(16, 16), 256>>>(Wo);

    attn_flash<<<dim3(SLEN / 128, NH), 256, ATTN_SMEM>>>(mask);

    outproj_wmma<<<dim3(EMB / 128, NB * SLEN / 128), 256, PROJ_SMEM>>>(bo, out);
}